// round 1
// baseline (speedup 1.0000x reference)
#include <cuda_runtime.h>
#include <math.h>

#define Nn    4096
#define INF   512
#define OUTF  128
#define CN    16384          // C * N rows of attention
#define TOTD  67108864.0     // CN * Nn
#define SCALE 2.5f           // 1/(1-0.6)

// ---------------- scratch (static device memory only; no allocations) ----------------
__device__ float  g_h[Nn * OUTF];        // h = x @ W^T
__device__ float  g_g[Nn * OUTF];        // g = h * (2.5/S[j])
__device__ float  g_Wt[INF * OUTF];      // W transposed to [k][f]
__device__ double g_part[1024];          // mean partials
__device__ float  g_mean;
__device__ float  g_colpart[64 * Nn];    // column-sum partials (64 row-chunks)
__device__ float  g_rs[Nn];              // 2.5 / S[j]
__device__ int    g_mstride;             // 1 if mask is bool/u8, 4 if int32

// ---------------- mask dtype detection ----------------
__global__ void k_detect(const unsigned char* mask) {
    __shared__ int s[256];
    int nz = 0;
    for (int i = threadIdx.x; i < 65536; i += 256)
        if ((i & 3) != 0 && mask[i]) nz++;
    s[threadIdx.x] = nz;
    __syncthreads();
    for (int o = 128; o > 0; o >>= 1) {
        if (threadIdx.x < o) s[threadIdx.x] += s[threadIdx.x + o];
        __syncthreads();
    }
    if (threadIdx.x == 0) g_mstride = (s[0] == 0) ? 4 : 1;
}

// ---------------- W transpose: Wt[k][f] = W[f][k] ----------------
__global__ void k_wt(const float* __restrict__ W) {
    int o = blockIdx.x * 256 + threadIdx.x;   // 65536 total
    int f = o & (OUTF - 1);
    int k = o >> 7;
    g_Wt[o] = W[f * INF + k];
}

// ---------------- mean of attention (deterministic, double partials) ----------------
__global__ void k_meanpart(const float4* __restrict__ att4) {
    double acc = 0.0;
    int stride = gridDim.x * blockDim.x;
    int n4 = (CN * Nn) / 4;
    for (int i = blockIdx.x * blockDim.x + threadIdx.x; i < n4; i += stride) {
        float4 v = att4[i];
        acc += (double)((v.x + v.y) + (v.z + v.w));
    }
    __shared__ double s[256];
    s[threadIdx.x] = acc;
    __syncthreads();
    for (int o = 128; o > 0; o >>= 1) {
        if (threadIdx.x < o) s[threadIdx.x] += s[threadIdx.x + o];
        __syncthreads();
    }
    if (threadIdx.x == 0) g_part[blockIdx.x] = s[0];
}

__global__ void k_meanfin() {
    __shared__ double s[256];
    int t = threadIdx.x;
    double a = g_part[t] + g_part[t + 256] + g_part[t + 512] + g_part[t + 768];
    s[t] = a;
    __syncthreads();
    for (int o = 128; o > 0; o >>= 1) {
        if (t < o) s[t] += s[t + o];
        __syncthreads();
    }
    if (t == 0) g_mean = (float)(s[0] / TOTD);
}

// ---------------- column sums of exp-transformed attention ----------------
// grid (16 col-groups x 64 row-chunks), 256 threads; each thread one column, 256 rows.
__global__ void k_colsum(const float* __restrict__ att) {
    float mean = g_mean;
    int col = blockIdx.x * 256 + threadIdx.x;
    int r0 = blockIdx.y * 256;
    const float* p = att + (size_t)r0 * Nn + col;
    float acc = 0.f;
#pragma unroll 4
    for (int i = 0; i < 256; i++) {
        float v = p[(size_t)i * Nn];
        acc += (v > mean) ? __expf(v) : 0.f;
    }
    g_colpart[blockIdx.y * Nn + col] = acc;
}

__global__ void k_rs() {
    int j = blockIdx.x * 256 + threadIdx.x;
    float s = 0.f;
#pragma unroll 8
    for (int ch = 0; ch < 64; ch++) s += g_colpart[ch * Nn + j];
    g_rs[j] = SCALE / s;
}

// ---------------- g[j][f] = h[j][f] * rs[j] ----------------
__global__ void k_gfold() {
    int i = blockIdx.x * 256 + threadIdx.x;   // 524288 total
    g_g[i] = g_h[i] * g_rs[i >> 7];
}

// ---------------- GEMM1: h = x @ Wt  (M=4096, K=512, N=128) ----------------
__global__ __launch_bounds__(128) void k_gemm1(const float* __restrict__ x) {
    __shared__ __align__(16) float As[16][64];
    __shared__ __align__(16) float Bs[16][128];
    int tid = threadIdx.x;
    int r0 = blockIdx.x * 64;
    int lane = tid & 31, warp = tid >> 5;
    int tc = lane >> 1;               // 0..15
    int tr = (warp << 1) | (lane & 1); // 0..7
    float acc[64];
#pragma unroll
    for (int i = 0; i < 64; i++) acc[i] = 0.f;

    for (int k0 = 0; k0 < INF; k0 += 16) {
#pragma unroll
        for (int q8 = 0; q8 < 2; q8++) {
            int q = tid + q8 * 128;       // float4 index in [0,256)
            int row = q >> 2, c4 = q & 3;
            float4 v = *(const float4*)(x + (size_t)(r0 + row) * INF + k0 + c4 * 4);
            As[c4 * 4 + 0][row] = v.x;
            As[c4 * 4 + 1][row] = v.y;
            As[c4 * 4 + 2][row] = v.z;
            As[c4 * 4 + 3][row] = v.w;
        }
#pragma unroll
        for (int q4 = 0; q4 < 4; q4++) {
            int q = tid + q4 * 128;       // float4 index in [0,512)
            int kk = q >> 5, f4 = q & 31;
            *(float4*)&Bs[kk][f4 * 4] =
                *(const float4*)(g_Wt + (k0 + kk) * OUTF + f4 * 4);
        }
        __syncthreads();
#pragma unroll
        for (int kk = 0; kk < 16; kk++) {
            float a[8], b[8];
            *(float4*)(a)     = *(const float4*)&As[kk][tr * 8];
            *(float4*)(a + 4) = *(const float4*)&As[kk][tr * 8 + 4];
            *(float4*)(b)     = *(const float4*)&Bs[kk][tc * 8];
            *(float4*)(b + 4) = *(const float4*)&Bs[kk][tc * 8 + 4];
#pragma unroll
            for (int i = 0; i < 8; i++)
#pragma unroll
                for (int j = 0; j < 8; j++) acc[i * 8 + j] += a[i] * b[j];
        }
        __syncthreads();
    }
#pragma unroll
    for (int i = 0; i < 8; i++) {
        int r = r0 + tr * 8 + i;
        float* op = g_h + (size_t)r * OUTF + tc * 8;
        *(float4*)op = make_float4(acc[i * 8 + 0], acc[i * 8 + 1], acc[i * 8 + 2], acc[i * 8 + 3]);
        *(float4*)(op + 4) = make_float4(acc[i * 8 + 4], acc[i * 8 + 5], acc[i * 8 + 6], acc[i * 8 + 7]);
    }
}

// ---------------- GEMM2: out = A @ g, A computed on the fly ----------------
// A[r,j] = (mask[r,j] && att[r,j] > mean) ? exp(att[r,j]) : 0
// out[n, c*128+f] with r = c*4096 + n.
__global__ __launch_bounds__(128) void k_gemm2(const float* __restrict__ att,
                                               const unsigned char* __restrict__ mask,
                                               float* __restrict__ out) {
    __shared__ __align__(16) float As[16][64];
    __shared__ __align__(16) float Bs[16][128];
    float mean = g_mean;
    int mstride = g_mstride;
    int tid = threadIdx.x;
    int r0 = blockIdx.x * 64;
    int lane = tid & 31, warp = tid >> 5;
    int tc = lane >> 1;
    int tr = (warp << 1) | (lane & 1);
    float acc[64];
#pragma unroll
    for (int i = 0; i < 64; i++) acc[i] = 0.f;

    for (int k0 = 0; k0 < Nn; k0 += 16) {
#pragma unroll
        for (int q8 = 0; q8 < 2; q8++) {
            int q = tid + q8 * 128;
            int row = q >> 2, c4 = q & 3;
            size_t gidx = (size_t)(r0 + row) * Nn + k0 + c4 * 4;
            float4 v = *(const float4*)(att + gidx);
            unsigned int m0, m1, m2, m3;
            if (mstride == 1) {
                uchar4 mm = *(const uchar4*)(mask + gidx);
                m0 = mm.x; m1 = mm.y; m2 = mm.z; m3 = mm.w;
            } else {
                int4 mi = *(const int4*)((const int*)mask + gidx);
                m0 = mi.x; m1 = mi.y; m2 = mi.z; m3 = mi.w;
            }
            As[c4 * 4 + 0][row] = (m0 && v.x > mean) ? __expf(v.x) : 0.f;
            As[c4 * 4 + 1][row] = (m1 && v.y > mean) ? __expf(v.y) : 0.f;
            As[c4 * 4 + 2][row] = (m2 && v.z > mean) ? __expf(v.z) : 0.f;
            As[c4 * 4 + 3][row] = (m3 && v.w > mean) ? __expf(v.w) : 0.f;
        }
#pragma unroll
        for (int q4 = 0; q4 < 4; q4++) {
            int q = tid + q4 * 128;
            int kk = q >> 5, f4 = q & 31;
            *(float4*)&Bs[kk][f4 * 4] =
                *(const float4*)(g_g + (k0 + kk) * OUTF + f4 * 4);
        }
        __syncthreads();
#pragma unroll
        for (int kk = 0; kk < 16; kk++) {
            float a[8], b[8];
            *(float4*)(a)     = *(const float4*)&As[kk][tr * 8];
            *(float4*)(a + 4) = *(const float4*)&As[kk][tr * 8 + 4];
            *(float4*)(b)     = *(const float4*)&Bs[kk][tc * 8];
            *(float4*)(b + 4) = *(const float4*)&Bs[kk][tc * 8 + 4];
#pragma unroll
            for (int i = 0; i < 8; i++)
#pragma unroll
                for (int j = 0; j < 8; j++) acc[i * 8 + j] += a[i] * b[j];
        }
        __syncthreads();
    }
#pragma unroll
    for (int i = 0; i < 8; i++) {
        int r = r0 + tr * 8 + i;
        int n = r & (Nn - 1);
        int c = r >> 12;
        float* op = out + (size_t)n * (4 * OUTF) + c * OUTF + tc * 8;
        *(float4*)op = make_float4(acc[i * 8 + 0], acc[i * 8 + 1], acc[i * 8 + 2], acc[i * 8 + 3]);
        *(float4*)(op + 4) = make_float4(acc[i * 8 + 4], acc[i * 8 + 5], acc[i * 8 + 6], acc[i * 8 + 7]);
    }
}

// ---------------- launch ----------------
extern "C" void kernel_launch(void* const* d_in, const int* in_sizes, int n_in,
                              void* d_out, int out_size) {
    const float* x = (const float*)d_in[0];
    const float* att = (const float*)d_in[1];
    const float* W = (const float*)d_in[2];
    const unsigned char* mask = (const unsigned char*)d_in[3];
    float* out = (float*)d_out;

    k_detect<<<1, 256>>>(mask);
    k_wt<<<256, 256>>>(W);
    k_gemm1<<<64, 128>>>(x);
    k_meanpart<<<1024, 256>>>((const float4*)att);
    k_meanfin<<<1, 256>>>();
    k_colsum<<<dim3(16, 64), 256>>>(att);
    k_rs<<<16, 256>>>();
    k_gfold<<<2048, 256>>>();
    k_gemm2<<<256, 128>>>(att, mask, out);
}

// round 3
// speedup vs baseline: 1.1904x; 1.1904x over previous
#include <cuda_runtime.h>
#include <math.h>

#define Nn    4096
#define INF   512
#define OUTF  128
#define CN    16384          // C * N rows of attention
#define TOTD  67108864.0     // CN * Nn
#define SCALE 2.5f           // 1/(1-0.6)

typedef unsigned long long ull;

__device__ __forceinline__ ull pack2(float x) {
    ull r; asm("mov.b64 %0,{%1,%1};" : "=l"(r) : "f"(x)); return r;
}
__device__ __forceinline__ ull fma2(ull a, ull b, ull c) {
    ull d; asm("fma.rn.f32x2 %0,%1,%2,%3;" : "=l"(d) : "l"(a), "l"(b), "l"(c)); return d;
}

// ---------------- scratch (static device memory only) ----------------
__device__ float  g_h[Nn * OUTF];        // h = x @ W^T
__device__ float  g_g[Nn * OUTF];        // g = h * (2.5/S[j])
__device__ float  g_Wt[INF * OUTF];      // W transposed to [k][f]
__device__ double g_part[1024];          // mean partials
__device__ float  g_mean;
__device__ float  g_colpart[64 * Nn];    // column-sum partials
__device__ int    g_mstride;             // 1 if mask is bool/u8, 4 if int32

// ---------------- mask dtype detection ----------------
__global__ void k_detect(const unsigned char* mask) {
    __shared__ int s[256];
    int nz = 0;
    for (int i = threadIdx.x; i < 65536; i += 256)
        if ((i & 3) != 0 && mask[i]) nz++;
    s[threadIdx.x] = nz;
    __syncthreads();
    for (int o = 128; o > 0; o >>= 1) {
        if (threadIdx.x < o) s[threadIdx.x] += s[threadIdx.x + o];
        __syncthreads();
    }
    if (threadIdx.x == 0) g_mstride = (s[0] == 0) ? 4 : 1;
}

// ---------------- W transpose ----------------
__global__ void k_wt(const float* __restrict__ W) {
    int o = blockIdx.x * 256 + threadIdx.x;
    int f = o & (OUTF - 1);
    int k = o >> 7;
    g_Wt[o] = W[f * INF + k];
}

// ---------------- mean of attention: float per-thread, double reduce ----------------
__global__ void k_meanpart(const float4* __restrict__ att4) {
    float acc = 0.f;
    int stride = gridDim.x * blockDim.x;
    int n4 = (CN * Nn) / 4;
#pragma unroll 4
    for (int i = blockIdx.x * blockDim.x + threadIdx.x; i < n4; i += stride) {
        float4 v = att4[i];
        acc += (v.x + v.y) + (v.z + v.w);
    }
    __shared__ double s[256];
    s[threadIdx.x] = (double)acc;
    __syncthreads();
    for (int o = 128; o > 0; o >>= 1) {
        if (threadIdx.x < o) s[threadIdx.x] += s[threadIdx.x + o];
        __syncthreads();
    }
    if (threadIdx.x == 0) g_part[blockIdx.x] = s[0];
}

__global__ void k_meanfin() {
    __shared__ double s[256];
    int t = threadIdx.x;
    double a = g_part[t] + g_part[t + 256] + g_part[t + 512] + g_part[t + 768];
    s[t] = a;
    __syncthreads();
    for (int o = 128; o > 0; o >>= 1) {
        if (t < o) s[t] += s[t + o];
        __syncthreads();
    }
    if (t == 0) g_mean = (float)(s[0] / TOTD);
}

// ---------------- column sums of exp-transformed attention ----------------
__global__ void k_colsum(const float* __restrict__ att) {
    float mean = g_mean;
    int col = blockIdx.x * 256 + threadIdx.x;
    int r0 = blockIdx.y * 256;
    const float* p = att + (size_t)r0 * Nn + col;
    float acc = 0.f;
#pragma unroll 4
    for (int i = 0; i < 256; i++) {
        float v = p[(size_t)i * Nn];
        acc += (v > mean) ? __expf(v) : 0.f;
    }
    g_colpart[blockIdx.y * Nn + col] = acc;
}

// ---------------- rs + g fold fused: g[j][f] = h[j][f] * (2.5/S[j]) ----------------
// grid 128 blocks x 256 threads; block handles 32 j rows (32*128 = 4096 elems)
__global__ void k_rsg() {
    __shared__ float rs[32];
    int j0 = blockIdx.x * 32;
    if (threadIdx.x < 32) {
        int j = j0 + threadIdx.x;
        float s = 0.f;
#pragma unroll 8
        for (int ch = 0; ch < 64; ch++) s += g_colpart[ch * Nn + j];
        rs[threadIdx.x] = SCALE / s;
    }
    __syncthreads();
#pragma unroll
    for (int q = 0; q < 16; q++) {
        int i = q * 256 + threadIdx.x;        // 0..4095
        int jj = i >> 7;
        g_g[(size_t)j0 * OUTF + i] = g_h[(size_t)j0 * OUTF + i] * rs[jj];
    }
}

// ---------------- GEMM1: h = x @ Wt  (M=4096, K=512, N=128) ----------------
__global__ __launch_bounds__(128) void k_gemm1(const float* __restrict__ x) {
    __shared__ __align__(16) float As[16][64];
    __shared__ __align__(16) float Bs[16][128];
    int tid = threadIdx.x;
    int r0 = blockIdx.x * 64;
    int lane = tid & 31, warp = tid >> 5;
    int tc = lane >> 1;
    int tr = (warp << 1) | (lane & 1);
    float acc[64];
#pragma unroll
    for (int i = 0; i < 64; i++) acc[i] = 0.f;

    for (int k0 = 0; k0 < INF; k0 += 16) {
#pragma unroll
        for (int q8 = 0; q8 < 2; q8++) {
            int q = tid + q8 * 128;
            int row = q >> 2, c4 = q & 3;
            float4 v = *(const float4*)(x + (size_t)(r0 + row) * INF + k0 + c4 * 4);
            As[c4 * 4 + 0][row] = v.x;
            As[c4 * 4 + 1][row] = v.y;
            As[c4 * 4 + 2][row] = v.z;
            As[c4 * 4 + 3][row] = v.w;
        }
#pragma unroll
        for (int q4 = 0; q4 < 4; q4++) {
            int q = tid + q4 * 128;
            int kk = q >> 5, f4 = q & 31;
            *(float4*)&Bs[kk][f4 * 4] =
                *(const float4*)(g_Wt + (k0 + kk) * OUTF + f4 * 4);
        }
        __syncthreads();
#pragma unroll
        for (int kk = 0; kk < 16; kk++) {
            float a[8], b[8];
            *(float4*)(a)     = *(const float4*)&As[kk][tr * 8];
            *(float4*)(a + 4) = *(const float4*)&As[kk][tr * 8 + 4];
            *(float4*)(b)     = *(const float4*)&Bs[kk][tc * 8];
            *(float4*)(b + 4) = *(const float4*)&Bs[kk][tc * 8 + 4];
#pragma unroll
            for (int i = 0; i < 8; i++)
#pragma unroll
                for (int j = 0; j < 8; j++) acc[i * 8 + j] += a[i] * b[j];
        }
        __syncthreads();
    }
#pragma unroll
    for (int i = 0; i < 8; i++) {
        int r = r0 + tr * 8 + i;
        float* op = g_h + (size_t)r * OUTF + tc * 8;
        *(float4*)op = make_float4(acc[i * 8 + 0], acc[i * 8 + 1], acc[i * 8 + 2], acc[i * 8 + 3]);
        *(float4*)(op + 4) = make_float4(acc[i * 8 + 4], acc[i * 8 + 5], acc[i * 8 + 6], acc[i * 8 + 7]);
    }
}

// ---------------- GEMM2: out = A @ g with packed f32x2 FMA + reg prefetch ----------------
// A[r,j] = (mask[r,j] && att[r,j] > mean) ? exp(att[r,j]) : 0
// out[n, c*128+f], r = c*4096 + n.
__global__ __launch_bounds__(128) void k_gemm2(const float* __restrict__ att,
                                               const unsigned char* __restrict__ mask,
                                               float* __restrict__ out) {
    __shared__ __align__(16) float As[16][64];
    __shared__ __align__(16) float Bs[16][128];
    float mean = g_mean;
    int mstride = g_mstride;
    int tid = threadIdx.x;
    int r0 = blockIdx.x * 64;
    int lane = tid & 31, warp = tid >> 5;
    int tc = lane >> 1;                 // 0..15 : col pair-group (8 floats)
    int tr = (warp << 1) | (lane & 1);  // 0..7  : row group (8 rows)

    ull acc[32];                        // [i][jp] : 8 rows x 4 col-pairs
#pragma unroll
    for (int i = 0; i < 32; i++) acc[i] = 0ULL;

    // prefetch registers
    float4 va[2]; uint4 vm[2]; float4 vb[4];
    // per-thread addressing for the A tile (2 float4s) and B tile (4 float4s)
    int arow0 = tid >> 2, ac4 = tid & 3;            // q8=0
    int arow1 = (tid + 128) >> 2;                   // q8=1 (same ac4)

    #define LOADG(k0_)                                                              \
    {                                                                               \
        size_t gA0 = (size_t)(r0 + arow0) * Nn + (k0_) + ac4 * 4;                   \
        size_t gA1 = (size_t)(r0 + arow1) * Nn + (k0_) + ac4 * 4;                   \
        va[0] = *(const float4*)(att + gA0);                                        \
        va[1] = *(const float4*)(att + gA1);                                        \
        if (mstride == 1) {                                                         \
            uchar4 m0 = *(const uchar4*)(mask + gA0);                               \
            uchar4 m1 = *(const uchar4*)(mask + gA1);                               \
            vm[0] = make_uint4(m0.x, m0.y, m0.z, m0.w);                             \
            vm[1] = make_uint4(m1.x, m1.y, m1.z, m1.w);                             \
        } else {                                                                    \
            int4 m0 = *(const int4*)((const int*)mask + gA0);                       \
            int4 m1 = *(const int4*)((const int*)mask + gA1);                       \
            vm[0] = make_uint4(m0.x, m0.y, m0.z, m0.w);                             \
            vm[1] = make_uint4(m1.x, m1.y, m1.z, m1.w);                             \
        }                                                                           \
        _Pragma("unroll")                                                           \
        for (int q4 = 0; q4 < 4; q4++) {                                            \
            int q = tid + q4 * 128;                                                 \
            int kk = q >> 5, f4 = q & 31;                                           \
            vb[q4] = *(const float4*)(g_g + ((k0_) + kk) * OUTF + f4 * 4);          \
        }                                                                           \
    }

    #define STORES()                                                                \
    {                                                                               \
        _Pragma("unroll")                                                           \
        for (int q8 = 0; q8 < 2; q8++) {                                            \
            int row = (q8 == 0) ? arow0 : arow1;                                    \
            float4 v = va[q8]; uint4 m = vm[q8];                                    \
            As[ac4 * 4 + 0][row] = (m.x && v.x > mean) ? __expf(v.x) : 0.f;         \
            As[ac4 * 4 + 1][row] = (m.y && v.y > mean) ? __expf(v.y) : 0.f;         \
            As[ac4 * 4 + 2][row] = (m.z && v.z > mean) ? __expf(v.z) : 0.f;         \
            As[ac4 * 4 + 3][row] = (m.w && v.w > mean) ? __expf(v.w) : 0.f;         \
        }                                                                           \
        _Pragma("unroll")                                                           \
        for (int q4 = 0; q4 < 4; q4++) {                                            \
            int q = tid + q4 * 128;                                                 \
            int kk = q >> 5, f4 = q & 31;                                           \
            *(float4*)&Bs[kk][f4 * 4] = vb[q4];                                     \
        }                                                                           \
    }

    LOADG(0);
    STORES();
    __syncthreads();

    for (int k0 = 16; k0 <= Nn; k0 += 16) {
        if (k0 < Nn) LOADG(k0);
#pragma unroll
        for (int kk = 0; kk < 16; kk++) {
            ulonglong2 b01 = *(const ulonglong2*)&Bs[kk][tc * 8];
            ulonglong2 b23 = *(const ulonglong2*)&Bs[kk][tc * 8 + 4];
            float4 alo = *(const float4*)&As[kk][tr * 8];
            float4 ahi = *(const float4*)&As[kk][tr * 8 + 4];
            float av[8] = {alo.x, alo.y, alo.z, alo.w, ahi.x, ahi.y, ahi.z, ahi.w};
#pragma unroll
            for (int i = 0; i < 8; i++) {
                ull ad = pack2(av[i]);
                acc[i * 4 + 0] = fma2(ad, b01.x, acc[i * 4 + 0]);
                acc[i * 4 + 1] = fma2(ad, b01.y, acc[i * 4 + 1]);
                acc[i * 4 + 2] = fma2(ad, b23.x, acc[i * 4 + 2]);
                acc[i * 4 + 3] = fma2(ad, b23.y, acc[i * 4 + 3]);
            }
        }
        __syncthreads();
        if (k0 < Nn) {
            STORES();
            __syncthreads();
        }
    }

#pragma unroll
    for (int i = 0; i < 8; i++) {
        int r = r0 + tr * 8 + i;
        int n = r & (Nn - 1);
        int c = r >> 12;
        float o[8];
#pragma unroll
        for (int jp = 0; jp < 4; jp++)
            asm("mov.b64 {%0,%1},%2;" : "=f"(o[2 * jp]), "=f"(o[2 * jp + 1]) : "l"(acc[i * 4 + jp]));
        float* op = out + (size_t)n * (4 * OUTF) + c * OUTF + tc * 8;
        *(float4*)op       = make_float4(o[0], o[1], o[2], o[3]);
        *(float4*)(op + 4) = make_float4(o[4], o[5], o[6], o[7]);
    }
    #undef LOADG
    #undef STORES
}

// ---------------- launch ----------------
extern "C" void kernel_launch(void* const* d_in, const int* in_sizes, int n_in,
                              void* d_out, int out_size) {
    const float* x = (const float*)d_in[0];
    const float* att = (const float*)d_in[1];
    const float* W = (const float*)d_in[2];
    const unsigned char* mask = (const unsigned char*)d_in[3];
    float* out = (float*)d_out;

    k_detect<<<1, 256>>>(mask);
    k_wt<<<256, 256>>>(W);
    k_gemm1<<<64, 128>>>(x);
    k_meanpart<<<1024, 256>>>((const float4*)att);
    k_meanfin<<<1, 256>>>();
    k_colsum<<<dim3(16, 64), 256>>>(att);
    k_rsg<<<128, 256>>>();
    k_gemm2<<<256, 128>>>(att, mask, out);
}

// round 5
// speedup vs baseline: 1.8162x; 1.5258x over previous
#include <cuda_runtime.h>
#include <cuda_bf16.h>
#include <stdint.h>
#include <math.h>

#define Nn    4096
#define INF   512
#define OUTF  128
#define CN    16384
#define TOTD  67108864.0
#define SCALE 2.5f
#define KC    64
#define NCHUNK 64

__device__ __forceinline__ uint32_t smem_to_u32(const void* p) {
    uint32_t a;
    asm("{ .reg .u64 t; cvta.to.shared.u64 t, %1; cvt.u32.u64 %0, t; }" : "=r"(a) : "l"(p));
    return a;
}
#define LDSM4(r, a)                                                                   \
    asm volatile("ldmatrix.sync.aligned.m8n8.x4.shared.b16 {%0,%1,%2,%3}, [%4];"      \
        : "=r"((r)[0]), "=r"((r)[1]), "=r"((r)[2]), "=r"((r)[3]) : "r"(a))
#define MMA16816(d, a, b0, b1)                                                        \
    asm volatile("mma.sync.aligned.m16n8k16.row.col.f32.bf16.bf16.f32 "               \
        "{%0,%1,%2,%3},{%4,%5,%6,%7},{%8,%9},{%0,%1,%2,%3};"                          \
        : "+f"((d)[0]), "+f"((d)[1]), "+f"((d)[2]), "+f"((d)[3])                      \
        : "r"((a)[0]), "r"((a)[1]), "r"((a)[2]), "r"((a)[3]), "r"(b0), "r"(b1))
#define CPASYNC16(dst, src)                                                           \
    asm volatile("cp.async.cg.shared.global [%0], [%1], 16;" :: "r"(dst), "l"(src))
#define CPCOMMIT() asm volatile("cp.async.commit_group;" ::: "memory")
#define CPWAIT0()  asm volatile("cp.async.wait_group 0;" ::: "memory")

__device__ __forceinline__ uint32_t swz(uint32_t off) { return off ^ ((off >> 3) & 0x70); }

// ---------------- scratch ----------------
__device__ float  g_h[Nn * OUTF];
__device__ float  g_Wt[INF * OUTF];
__device__ double g_part[1024];
__device__ float  g_mean;
__device__ float  g_colpart[64 * Nn];
__device__ float  g_rs[Nn];
__device__ int    g_mstride;
__device__ unsigned short g_Bh[OUTF * Nn];   // [f][k] bf16 of g[k][f]
__device__ unsigned short g_Bl[OUTF * Nn];   // residual

// ---------------- mask dtype detection ----------------
__global__ void k_detect(const unsigned char* mask) {
    __shared__ int s[256];
    int nz = 0;
    for (int i = threadIdx.x; i < 65536; i += 256)
        if ((i & 3) != 0 && mask[i]) nz++;
    s[threadIdx.x] = nz;
    __syncthreads();
    for (int o = 128; o > 0; o >>= 1) {
        if (threadIdx.x < o) s[threadIdx.x] += s[threadIdx.x + o];
        __syncthreads();
    }
    if (threadIdx.x == 0) g_mstride = (s[0] == 0) ? 4 : 1;
}

// ---------------- W transpose ----------------
__global__ void k_wt(const float* __restrict__ W) {
    int o = blockIdx.x * 256 + threadIdx.x;
    int f = o & (OUTF - 1);
    int k = o >> 7;
    g_Wt[o] = W[f * INF + k];
}

// ---------------- mean ----------------
__global__ void k_meanpart(const float4* __restrict__ att4) {
    float acc = 0.f;
    int stride = gridDim.x * blockDim.x;
    int n4 = (CN * Nn) / 4;
#pragma unroll 4
    for (int i = blockIdx.x * blockDim.x + threadIdx.x; i < n4; i += stride) {
        float4 v = att4[i];
        acc += (v.x + v.y) + (v.z + v.w);
    }
    __shared__ double s[256];
    s[threadIdx.x] = (double)acc;
    __syncthreads();
    for (int o = 128; o > 0; o >>= 1) {
        if (threadIdx.x < o) s[threadIdx.x] += s[threadIdx.x + o];
        __syncthreads();
    }
    if (threadIdx.x == 0) g_part[blockIdx.x] = s[0];
}

__global__ void k_meanfin() {
    __shared__ double s[256];
    int t = threadIdx.x;
    double a = g_part[t] + g_part[t + 256] + g_part[t + 512] + g_part[t + 768];
    s[t] = a;
    __syncthreads();
    for (int o = 128; o > 0; o >>= 1) {
        if (t < o) s[t] += s[t + o];
        __syncthreads();
    }
    if (t == 0) g_mean = (float)(s[0] / TOTD);
}

// ---------------- column sums ----------------
__global__ void k_colsum(const float* __restrict__ att) {
    float mean = g_mean;
    int col = blockIdx.x * 256 + threadIdx.x;
    int r0 = blockIdx.y * 256;
    const float* p = att + (size_t)r0 * Nn + col;
    float acc = 0.f;
#pragma unroll 4
    for (int i = 0; i < 256; i++) {
        float v = p[(size_t)i * Nn];
        acc += (v > mean) ? __expf(v) : 0.f;
    }
    g_colpart[blockIdx.y * Nn + col] = acc;
}

__global__ void k_rs() {
    int j = blockIdx.x * 256 + threadIdx.x;
    float s = 0.f;
#pragma unroll 8
    for (int ch = 0; ch < 64; ch++) s += g_colpart[ch * Nn + j];
    g_rs[j] = SCALE / s;
}

// ---------------- GEMM1: h = x @ Wt ----------------
__global__ __launch_bounds__(128) void k_gemm1(const float* __restrict__ x) {
    __shared__ __align__(16) float As[16][64];
    __shared__ __align__(16) float Bs[16][128];
    int tid = threadIdx.x;
    int r0 = blockIdx.x * 64;
    int lane = tid & 31, warp = tid >> 5;
    int tc = lane >> 1;
    int tr = (warp << 1) | (lane & 1);
    float acc[64];
#pragma unroll
    for (int i = 0; i < 64; i++) acc[i] = 0.f;

    for (int k0 = 0; k0 < INF; k0 += 16) {
#pragma unroll
        for (int q8 = 0; q8 < 2; q8++) {
            int q = tid + q8 * 128;
            int row = q >> 2, c4 = q & 3;
            float4 v = *(const float4*)(x + (size_t)(r0 + row) * INF + k0 + c4 * 4);
            As[c4 * 4 + 0][row] = v.x;
            As[c4 * 4 + 1][row] = v.y;
            As[c4 * 4 + 2][row] = v.z;
            As[c4 * 4 + 3][row] = v.w;
        }
#pragma unroll
        for (int q4 = 0; q4 < 4; q4++) {
            int q = tid + q4 * 128;
            int kk = q >> 5, f4 = q & 31;
            *(float4*)&Bs[kk][f4 * 4] = *(const float4*)(g_Wt + (k0 + kk) * OUTF + f4 * 4);
        }
        __syncthreads();
#pragma unroll
        for (int kk = 0; kk < 16; kk++) {
            float a[8], b[8];
            *(float4*)(a)     = *(const float4*)&As[kk][tr * 8];
            *(float4*)(a + 4) = *(const float4*)&As[kk][tr * 8 + 4];
            *(float4*)(b)     = *(const float4*)&Bs[kk][tc * 8];
            *(float4*)(b + 4) = *(const float4*)&Bs[kk][tc * 8 + 4];
#pragma unroll
            for (int i = 0; i < 8; i++)
#pragma unroll
                for (int j = 0; j < 8; j++) acc[i * 8 + j] += a[i] * b[j];
        }
        __syncthreads();
    }
#pragma unroll
    for (int i = 0; i < 8; i++) {
        int r = r0 + tr * 8 + i;
        float* op = g_h + (size_t)r * OUTF + tc * 8;
        *(float4*)op = make_float4(acc[i * 8 + 0], acc[i * 8 + 1], acc[i * 8 + 2], acc[i * 8 + 3]);
        *(float4*)(op + 4) = make_float4(acc[i * 8 + 4], acc[i * 8 + 5], acc[i * 8 + 6], acc[i * 8 + 7]);
    }
}

// ---------------- B prep: Bh/Bl[f][k] = bf16split(h[k][f] * rs[k]) ----------------
__global__ void k_bprep() {
    __shared__ float tile[32][33];
    __shared__ float rss[32];
    int k0 = blockIdx.x * 32, f0 = blockIdx.y * 32;
    int t = threadIdx.x;
    {
        int ki = t >> 3, f4 = (t & 7) * 4;
        float4 v = *(const float4*)(g_h + (size_t)(k0 + ki) * OUTF + f0 + f4);
        tile[ki][f4 + 0] = v.x; tile[ki][f4 + 1] = v.y;
        tile[ki][f4 + 2] = v.z; tile[ki][f4 + 3] = v.w;
    }
    if (t < 32) rss[t] = g_rs[k0 + t];
    __syncthreads();
    int fi = t >> 3, k4 = (t & 7) * 4;
    unsigned short hs[4], ls[4];
#pragma unroll
    for (int j = 0; j < 4; j++) {
        float a = tile[k4 + j][fi] * rss[k4 + j];
        __nv_bfloat16 hb = __float2bfloat16_rn(a);
        float rem = a - __bfloat162float(hb);
        __nv_bfloat16 lb = __float2bfloat16_rn(rem);
        hs[j] = __bfloat16_as_ushort(hb);
        ls[j] = __bfloat16_as_ushort(lb);
    }
    size_t o = (size_t)(f0 + fi) * Nn + k0 + k4;
    *(uint2*)(g_Bh + o) = make_uint2((uint32_t)hs[0] | ((uint32_t)hs[1] << 16),
                                     (uint32_t)hs[2] | ((uint32_t)hs[3] << 16));
    *(uint2*)(g_Bl + o) = make_uint2((uint32_t)ls[0] | ((uint32_t)ls[1] << 16),
                                     (uint32_t)ls[2] | ((uint32_t)ls[3] << 16));
}

// ---------------- GEMM2 via mma.sync bf16, 3-product split ----------------
// A[r,j] = (mask && att>mean) ? exp(att) : 0 -> Ah+Al bf16 on the fly.
// out = A @ g; block tile 128x128, warp tile 32x64, K-chunk 64, double buffered.
// SMEM stage layout (64KB/stage): Ah@0, Al@16K, Bh@32K, Bl@48K; stage1 @64K.
__global__ __launch_bounds__(256, 1) void k_gemm2m(const float* __restrict__ att,
                                                   const unsigned char* __restrict__ mask,
                                                   float* __restrict__ out) {
    extern __shared__ __align__(128) char sm[];
    uint32_t smb = smem_to_u32(sm);
    const int tid = threadIdx.x, lane = tid & 31, w = tid >> 5;
    const int r0 = blockIdx.x * 128;
    const float mean = g_mean;
    const int mstride = g_mstride;
    const int wm0 = (w & 3) * 32;
    const int wn0 = (w >> 2) * 64;

    float acc[2][8][4];
#pragma unroll
    for (int mt = 0; mt < 2; mt++)
#pragma unroll
        for (int nt = 0; nt < 8; nt++)
#pragma unroll
            for (int q = 0; q < 4; q++) acc[mt][nt][q] = 0.f;

    // fragment addressing (loop-invariant)
    const int li = lane >> 3;
    const uint32_t aRow = wm0 + (li & 1) * 8 + (lane & 7);
    const uint32_t aKof = (li >> 1) * 16;
    const uint32_t bRow = wn0 + ((lane >> 4) & 1) * 8 + (lane & 7);
    const uint32_t bKof = ((lane >> 3) & 1) * 16;

    // A-convert addressing: 32 elems/thread
    float4 va[8];
    uint32_t vmb[8];

#define LOADG(c_)                                                                     \
    {                                                                                 \
        _Pragma("unroll")                                                             \
        for (int i = 0; i < 8; i++) {                                                 \
            int idx = i * 256 + tid;                                                  \
            int m = idx >> 4, c4 = idx & 15;                                          \
            size_t g = (size_t)(r0 + m) * Nn + (c_) * KC + c4 * 4;                    \
            va[i] = *(const float4*)(att + g);                                        \
            if (mstride == 1) {                                                       \
                vmb[i] = *(const uint32_t*)(mask + g);                                \
            } else {                                                                  \
                int4 mi = *(const int4*)((const int*)mask + g);                       \
                vmb[i] = (mi.x ? 1u : 0u) | (mi.y ? 0x100u : 0u) |                    \
                         (mi.z ? 0x10000u : 0u) | (mi.w ? 0x1000000u : 0u);           \
            }                                                                         \
        }                                                                             \
    }

#define STORES(so_)                                                                   \
    {                                                                                 \
        _Pragma("unroll")                                                             \
        for (int i = 0; i < 8; i++) {                                                 \
            int idx = i * 256 + tid;                                                  \
            int m = idx >> 4, c4 = idx & 15;                                          \
            float4 v = va[i]; uint32_t mk = vmb[i];                                   \
            float a0 = ((mk & 0xFFu) && v.x > mean) ? __expf(v.x) : 0.f;              \
            float a1 = ((mk & 0xFF00u) && v.y > mean) ? __expf(v.y) : 0.f;            \
            float a2 = ((mk & 0xFF0000u) && v.z > mean) ? __expf(v.z) : 0.f;          \
            float a3 = ((mk & 0xFF000000u) && v.w > mean) ? __expf(v.w) : 0.f;        \
            float aa[4] = {a0, a1, a2, a3};                                           \
            unsigned short hs[4], ls[4];                                              \
            _Pragma("unroll")                                                         \
            for (int j = 0; j < 4; j++) {                                             \
                __nv_bfloat16 hb = __float2bfloat16_rn(aa[j]);                        \
                float rem = aa[j] - __bfloat162float(hb);                             \
                __nv_bfloat16 lb = __float2bfloat16_rn(rem);                          \
                hs[j] = __bfloat16_as_ushort(hb);                                     \
                ls[j] = __bfloat16_as_ushort(lb);                                     \
            }                                                                         \
            uint2 ph = make_uint2((uint32_t)hs[0] | ((uint32_t)hs[1] << 16),          \
                                  (uint32_t)hs[2] | ((uint32_t)hs[3] << 16));         \
            uint2 pl = make_uint2((uint32_t)ls[0] | ((uint32_t)ls[1] << 16),          \
                                  (uint32_t)ls[2] | ((uint32_t)ls[3] << 16));         \
            uint32_t sw = swz((uint32_t)(m * 128 + c4 * 8));                          \
            *(uint2*)(sm + (so_) + sw)         = ph;                                  \
            *(uint2*)(sm + (so_) + 16384 + sw) = pl;                                  \
        }                                                                             \
    }

#define CPB(c_, so_)                                                                  \
    {                                                                                 \
        _Pragma("unroll")                                                             \
        for (int i = 0; i < 4; i++) {                                                 \
            int g = i * 256 + tid;                                                    \
            int f = g >> 3, seg = g & 7;                                              \
            uint32_t sw = swz((uint32_t)(f * 128 + seg * 16));                        \
            const void* sh = (const void*)(g_Bh + (size_t)f * Nn + (c_) * KC + seg * 8); \
            const void* sl = (const void*)(g_Bl + (size_t)f * Nn + (c_) * KC + seg * 8); \
            CPASYNC16(smb + (so_) + 32768 + sw, sh);                                  \
            CPASYNC16(smb + (so_) + 49152 + sw, sl);                                  \
        }                                                                             \
    }

    // prologue: fill stage 0
    CPB(0, 0u);
    CPCOMMIT();
    LOADG(0);
    STORES(0u);
    CPWAIT0();
    __syncthreads();

    uint32_t so = 0;
    for (int c = 0; c < NCHUNK; c++) {
        uint32_t sn = so ^ 65536u;
        if (c < NCHUNK - 1) {
            CPB(c + 1, sn);
            CPCOMMIT();
            LOADG(c + 1);
        }
        // ---- MMA on stage so ----
#pragma unroll
        for (int ks = 0; ks < 4; ks++) {
            uint32_t ah[2][4], al[2][4];
#pragma unroll
            for (int mt = 0; mt < 2; mt++) {
                uint32_t off = (aRow + mt * 16) * 128 + ks * 32 + aKof;
                uint32_t sw = swz(off);
                LDSM4(ah[mt], smb + so + sw);
                LDSM4(al[mt], smb + so + 16384 + sw);
            }
#pragma unroll
            for (int nt2 = 0; nt2 < 4; nt2++) {
                uint32_t off = (bRow + nt2 * 16) * 128 + ks * 32 + bKof;
                uint32_t sw = swz(off);
                uint32_t bh[4], bl[4];
                LDSM4(bh, smb + so + 32768 + sw);
                LDSM4(bl, smb + so + 49152 + sw);
#pragma unroll
                for (int mt = 0; mt < 2; mt++) {
                    MMA16816(acc[mt][nt2 * 2],     ah[mt], bh[0], bh[1]);
                    MMA16816(acc[mt][nt2 * 2 + 1], ah[mt], bh[2], bh[3]);
                    MMA16816(acc[mt][nt2 * 2],     al[mt], bh[0], bh[1]);
                    MMA16816(acc[mt][nt2 * 2 + 1], al[mt], bh[2], bh[3]);
                    MMA16816(acc[mt][nt2 * 2],     ah[mt], bl[0], bl[1]);
                    MMA16816(acc[mt][nt2 * 2 + 1], ah[mt], bl[2], bl[3]);
                }
            }
        }
        if (c < NCHUNK - 1) {
            STORES(sn);
            CPWAIT0();
        }
        __syncthreads();
        so = sn;
    }

    // ---- epilogue: permuted store ----
    const int orow = lane >> 2, ocol = (lane & 3) * 2;
#pragma unroll
    for (int mt = 0; mt < 2; mt++) {
#pragma unroll
        for (int nt = 0; nt < 8; nt++) {
            int f = wn0 + nt * 8 + ocol;
            int r1 = r0 + wm0 + mt * 16 + orow;
            int n1 = r1 & (Nn - 1), c1 = r1 >> 12;
            *(float2*)(out + (size_t)n1 * 512 + c1 * OUTF + f) =
                make_float2(acc[mt][nt][0], acc[mt][nt][1]);
            int r2 = r1 + 8;
            int n2 = r2 & (Nn - 1), c2 = r2 >> 12;
            *(float2*)(out + (size_t)n2 * 512 + c2 * OUTF + f) =
                make_float2(acc[mt][nt][2], acc[mt][nt][3]);
        }
    }
#undef LOADG
#undef STORES
#undef CPB
}

// ---------------- launch ----------------
extern "C" void kernel_launch(void* const* d_in, const int* in_sizes, int n_in,
                              void* d_out, int out_size) {
    const float* x = (const float*)d_in[0];
    const float* att = (const float*)d_in[1];
    const float* W = (const float*)d_in[2];
    const unsigned char* mask = (const unsigned char*)d_in[3];
    float* out = (float*)d_out;

    static const int SMEM2 = 131072;
    cudaFuncSetAttribute(k_gemm2m, cudaFuncAttributeMaxDynamicSharedMemorySize, SMEM2);

    k_detect<<<1, 256>>>(mask);
    k_wt<<<256, 256>>>(W);
    k_gemm1<<<64, 128>>>(x);
    k_meanpart<<<1024, 256>>>((const float4*)att);
    k_meanfin<<<1, 256>>>();
    k_colsum<<<dim3(16, 64), 256>>>(att);
    k_rs<<<16, 256>>>();
    k_bprep<<<dim3(128, 4), 256>>>();
    k_gemm2m<<<128, 256, SMEM2>>>(att, mask, out);
}

// round 8
// speedup vs baseline: 2.4506x; 1.3493x over previous
#include <cuda_runtime.h>
#include <cuda_fp16.h>
#include <stdint.h>
#include <math.h>

#define Nn    4096
#define INF   512
#define OUTF  128
#define CN    16384
#define TOTD  67108864.0
#define SCALE 2.5f
#define KC    64
#define NCHUNK 64

__device__ __forceinline__ uint32_t smem_to_u32(const void* p) {
    uint32_t a;
    asm("{ .reg .u64 t; cvta.to.shared.u64 t, %1; cvt.u32.u64 %0, t; }" : "=r"(a) : "l"(p));
    return a;
}
__device__ __forceinline__ uint32_t packh2(float lo, float hi) {
    uint32_t r;
    asm("cvt.rn.f16x2.f32 %0, %1, %2;" : "=r"(r) : "f"(hi), "f"(lo));
    return r;
}
#define LDSM4(r, a)                                                                   \
    asm volatile("ldmatrix.sync.aligned.m8n8.x4.shared.b16 {%0,%1,%2,%3}, [%4];"      \
        : "=r"((r)[0]), "=r"((r)[1]), "=r"((r)[2]), "=r"((r)[3]) : "r"(a))
#define MMAH(d, a, b0, b1)                                                            \
    asm volatile("mma.sync.aligned.m16n8k16.row.col.f32.f16.f16.f32 "                 \
        "{%0,%1,%2,%3},{%4,%5,%6,%7},{%8,%9},{%0,%1,%2,%3};"                          \
        : "+f"((d)[0]), "+f"((d)[1]), "+f"((d)[2]), "+f"((d)[3])                      \
        : "r"((a)[0]), "r"((a)[1]), "r"((a)[2]), "r"((a)[3]), "r"(b0), "r"(b1))
#define CPASYNC16(dst, src)                                                           \
    asm volatile("cp.async.cg.shared.global [%0], [%1], 16;" :: "r"(dst), "l"(src))
#define CPCOMMIT() asm volatile("cp.async.commit_group;" ::: "memory")
#define CPWAIT0()  asm volatile("cp.async.wait_group 0;" ::: "memory")

__device__ __forceinline__ uint32_t swz(uint32_t off) { return off ^ ((off >> 3) & 0x70); }

// ---------------- scratch ----------------
__device__ float  g_h[Nn * OUTF];
__device__ float  g_Wt[INF * OUTF];
__device__ double g_part[1024];
__device__ float  g_mean;
__device__ float  g_colpart[64 * Nn];
__device__ float  g_rs[Nn];              // 1024 * 2.5 / S[j]
__device__ int    g_mstride;
__device__ unsigned short g_Bf[OUTF * Nn];   // [f][k] fp16 of g[k][f]*1024

// ---------------- mask dtype detection ----------------
__global__ void k_detect(const unsigned char* mask) {
    __shared__ int s[256];
    int nz = 0;
    for (int i = threadIdx.x; i < 65536; i += 256)
        if ((i & 3) != 0 && mask[i]) nz++;
    s[threadIdx.x] = nz;
    __syncthreads();
    for (int o = 128; o > 0; o >>= 1) {
        if (threadIdx.x < o) s[threadIdx.x] += s[threadIdx.x + o];
        __syncthreads();
    }
    if (threadIdx.x == 0) g_mstride = (s[0] == 0) ? 4 : 1;
}

// ---------------- W transpose ----------------
__global__ void k_wt(const float* __restrict__ W) {
    int o = blockIdx.x * 256 + threadIdx.x;
    int f = o & (OUTF - 1);
    int k = o >> 7;
    g_Wt[o] = W[f * INF + k];
}

// ---------------- mean ----------------
__global__ void k_meanpart(const float4* __restrict__ att4) {
    float acc = 0.f;
    int stride = gridDim.x * blockDim.x;
    int n4 = (CN * Nn) / 4;
#pragma unroll 4
    for (int i = blockIdx.x * blockDim.x + threadIdx.x; i < n4; i += stride) {
        float4 v = att4[i];
        acc += (v.x + v.y) + (v.z + v.w);
    }
    __shared__ double s[256];
    s[threadIdx.x] = (double)acc;
    __syncthreads();
    for (int o = 128; o > 0; o >>= 1) {
        if (threadIdx.x < o) s[threadIdx.x] += s[threadIdx.x + o];
        __syncthreads();
    }
    if (threadIdx.x == 0) g_part[blockIdx.x] = s[0];
}

__global__ void k_meanfin() {
    __shared__ double s[256];
    int t = threadIdx.x;
    double a = g_part[t] + g_part[t + 256] + g_part[t + 512] + g_part[t + 768];
    s[t] = a;
    __syncthreads();
    for (int o = 128; o > 0; o >>= 1) {
        if (t < o) s[t] += s[t + o];
        __syncthreads();
    }
    if (t == 0) g_mean = (float)(s[0] / TOTD);
}

// ---------------- column sums ----------------
__global__ void k_colsum(const float* __restrict__ att) {
    float mean = g_mean;
    int col = blockIdx.x * 256 + threadIdx.x;
    int r0 = blockIdx.y * 256;
    const float* p = att + (size_t)r0 * Nn + col;
    float acc = 0.f;
#pragma unroll 4
    for (int i = 0; i < 256; i++) {
        float v = p[(size_t)i * Nn];
        acc += (v > mean) ? __expf(v) : 0.f;
    }
    g_colpart[blockIdx.y * Nn + col] = acc;
}

__global__ void k_rs() {
    int j = blockIdx.x * 256 + threadIdx.x;
    float s = 0.f;
#pragma unroll 8
    for (int ch = 0; ch < 64; ch++) s += g_colpart[ch * Nn + j];
    g_rs[j] = 1024.f * SCALE / s;
}

// ---------------- GEMM1: h = x @ Wt  (BM=32, 256 threads, microtile 2x8) ----------------
__global__ __launch_bounds__(256) void k_gemm1(const float* __restrict__ x) {
    __shared__ __align__(16) float As[16][32];
    __shared__ __align__(16) float Bs[16][128];
    int tid = threadIdx.x;
    int r0 = blockIdx.x * 32;
    int tr = tid >> 4;        // 0..15 : row pair
    int tc = tid & 15;        // 0..15 : col group of 8
    float acc[2][8];
#pragma unroll
    for (int i = 0; i < 2; i++)
#pragma unroll
        for (int j = 0; j < 8; j++) acc[i][j] = 0.f;

    for (int k0 = 0; k0 < INF; k0 += 16) {
        if (tid < 128) {
            int row = tid >> 2, c4 = tid & 3;
            float4 v = *(const float4*)(x + (size_t)(r0 + row) * INF + k0 + c4 * 4);
            As[c4 * 4 + 0][row] = v.x;
            As[c4 * 4 + 1][row] = v.y;
            As[c4 * 4 + 2][row] = v.z;
            As[c4 * 4 + 3][row] = v.w;
        }
#pragma unroll
        for (int q = 0; q < 2; q++) {
            int g = tid + q * 256;
            int kk = g >> 5, f4 = g & 31;
            *(float4*)&Bs[kk][f4 * 4] = *(const float4*)(g_Wt + (k0 + kk) * OUTF + f4 * 4);
        }
        __syncthreads();
#pragma unroll
        for (int kk = 0; kk < 16; kk++) {
            float a0 = As[kk][tr * 2], a1 = As[kk][tr * 2 + 1];
            float b[8];
            *(float4*)(b)     = *(const float4*)&Bs[kk][tc * 8];
            *(float4*)(b + 4) = *(const float4*)&Bs[kk][tc * 8 + 4];
#pragma unroll
            for (int j = 0; j < 8; j++) {
                acc[0][j] += a0 * b[j];
                acc[1][j] += a1 * b[j];
            }
        }
        __syncthreads();
    }
#pragma unroll
    for (int i = 0; i < 2; i++) {
        float* op = g_h + (size_t)(r0 + tr * 2 + i) * OUTF + tc * 8;
        *(float4*)op       = make_float4(acc[i][0], acc[i][1], acc[i][2], acc[i][3]);
        *(float4*)(op + 4) = make_float4(acc[i][4], acc[i][5], acc[i][6], acc[i][7]);
    }
}

// ---------------- B prep: Bf[f][k] = fp16(h[k][f] * rs[k]) ----------------
__global__ void k_bprep() {
    __shared__ float tile[32][33];
    __shared__ float rss[32];
    int k0 = blockIdx.x * 32, f0 = blockIdx.y * 32;
    int t = threadIdx.x;
    {
        int ki = t >> 3, f4 = (t & 7) * 4;
        float4 v = *(const float4*)(g_h + (size_t)(k0 + ki) * OUTF + f0 + f4);
        tile[ki][f4 + 0] = v.x; tile[ki][f4 + 1] = v.y;
        tile[ki][f4 + 2] = v.z; tile[ki][f4 + 3] = v.w;
    }
    if (t < 32) rss[t] = g_rs[k0 + t];
    __syncthreads();
    int fi = t >> 3, k4 = (t & 7) * 4;
    uint32_t p01 = packh2(tile[k4 + 0][fi] * rss[k4 + 0], tile[k4 + 1][fi] * rss[k4 + 1]);
    uint32_t p23 = packh2(tile[k4 + 2][fi] * rss[k4 + 2], tile[k4 + 3][fi] * rss[k4 + 3]);
    size_t o = (size_t)(f0 + fi) * Nn + k0 + k4;
    *(uint2*)(g_Bf + o) = make_uint2(p01, p23);
}

// ---------------- GEMM2 via mma.sync fp16, single product ----------------
// A[r,j] = (mask && att>mean) ? exp(att) : 0 -> fp16 on the fly.
// out = (1/1024) * A @ Bf'; block tile 128x128, warp tile 32x64, K-chunk 64,
// double buffered. Stage = 32KB: Af@0, Bf@16K; stage1 @32K.
__global__ __launch_bounds__(256, 1) void k_gemm2m(const float* __restrict__ att,
                                                   const unsigned char* __restrict__ mask,
                                                   float* __restrict__ out) {
    extern __shared__ __align__(128) char sm[];
    uint32_t smb = smem_to_u32(sm);
    const int tid = threadIdx.x, lane = tid & 31, w = tid >> 5;
    const int r0 = blockIdx.x * 128;
    const float mean = g_mean;
    const int mstride = g_mstride;
    const int wm0 = (w & 3) * 32;
    const int wn0 = (w >> 2) * 64;

    float acc[2][8][4];
#pragma unroll
    for (int mt = 0; mt < 2; mt++)
#pragma unroll
        for (int nt = 0; nt < 8; nt++)
#pragma unroll
            for (int q = 0; q < 4; q++) acc[mt][nt][q] = 0.f;

    const int li = lane >> 3;
    const uint32_t aRow = wm0 + (li & 1) * 8 + (lane & 7);
    const uint32_t aKof = (li >> 1) * 16;
    const uint32_t bRow = wn0 + ((lane >> 4) & 1) * 8 + (lane & 7);
    const uint32_t bKof = ((lane >> 3) & 1) * 16;

    float4 va[8];
    uint32_t vmb[8];

#define LOADG(c_)                                                                     \
    {                                                                                 \
        _Pragma("unroll")                                                             \
        for (int i = 0; i < 8; i++) {                                                 \
            int idx = i * 256 + tid;                                                  \
            int m = idx >> 4, c4 = idx & 15;                                          \
            size_t g = (size_t)(r0 + m) * Nn + (c_) * KC + c4 * 4;                    \
            va[i] = *(const float4*)(att + g);                                        \
            if (mstride == 1) {                                                       \
                vmb[i] = *(const uint32_t*)(mask + g);                                \
            } else {                                                                  \
                int4 mi = *(const int4*)((const int*)mask + g);                       \
                vmb[i] = (mi.x ? 1u : 0u) | (mi.y ? 0x100u : 0u) |                    \
                         (mi.z ? 0x10000u : 0u) | (mi.w ? 0x1000000u : 0u);           \
            }                                                                         \
        }                                                                             \
    }

#define STORES(so_)                                                                   \
    {                                                                                 \
        _Pragma("unroll")                                                             \
        for (int i = 0; i < 8; i++) {                                                 \
            int idx = i * 256 + tid;                                                  \
            int m = idx >> 4, c4 = idx & 15;                                          \
            float4 v = va[i]; uint32_t mk = vmb[i];                                   \
            float a0 = ((mk & 0xFFu) && v.x > mean) ? __expf(v.x) : 0.f;              \
            float a1 = ((mk & 0xFF00u) && v.y > mean) ? __expf(v.y) : 0.f;            \
            float a2 = ((mk & 0xFF0000u) && v.z > mean) ? __expf(v.z) : 0.f;          \
            float a3 = ((mk & 0xFF000000u) && v.w > mean) ? __expf(v.w) : 0.f;        \
            uint32_t p01 = packh2(a0, a1);                                            \
            uint32_t p23 = packh2(a2, a3);                                            \
            uint32_t sw = swz((uint32_t)(m * 128 + c4 * 8));                          \
            *(uint2*)(sm + (so_) + sw) = make_uint2(p01, p23);                        \
        }                                                                             \
    }

#define CPB(c_, so_)                                                                  \
    {                                                                                 \
        _Pragma("unroll")                                                             \
        for (int i = 0; i < 4; i++) {                                                 \
            int g = i * 256 + tid;                                                    \
            int f = g >> 3, seg = g & 7;                                              \
            uint32_t sw = swz((uint32_t)(f * 128 + seg * 16));                        \
            const void* sh = (const void*)(g_Bf + (size_t)f * Nn + (c_) * KC + seg * 8); \
            CPASYNC16(smb + (so_) + 16384 + sw, sh);                                  \
        }                                                                             \
    }

    // prologue
    CPB(0, 0u);
    CPCOMMIT();
    LOADG(0);
    STORES(0u);
    CPWAIT0();
    __syncthreads();

    uint32_t so = 0;
    for (int c = 0; c < NCHUNK; c++) {
        uint32_t sn = so ^ 32768u;
        if (c < NCHUNK - 1) {
            CPB(c + 1, sn);
            CPCOMMIT();
            LOADG(c + 1);
        }
#pragma unroll
        for (int ks = 0; ks < 4; ks++) {
            uint32_t ah[2][4];
#pragma unroll
            for (int mt = 0; mt < 2; mt++) {
                uint32_t sw = swz((aRow + mt * 16) * 128 + ks * 32 + aKof);
                LDSM4(ah[mt], smb + so + sw);
            }
#pragma unroll
            for (int nt2 = 0; nt2 < 4; nt2++) {
                uint32_t sw = swz((bRow + nt2 * 16) * 128 + ks * 32 + bKof);
                uint32_t bh[4];
                LDSM4(bh, smb + so + 16384 + sw);
#pragma unroll
                for (int mt = 0; mt < 2; mt++) {
                    MMAH(acc[mt][nt2 * 2],     ah[mt], bh[0], bh[1]);
                    MMAH(acc[mt][nt2 * 2 + 1], ah[mt], bh[2], bh[3]);
                }
            }
        }
        if (c < NCHUNK - 1) {
            STORES(sn);
            CPWAIT0();
        }
        __syncthreads();
        so = sn;
    }

    // epilogue: unscale + permuted store
    const float dsc = 1.f / 1024.f;
    const int orow = lane >> 2, ocol = (lane & 3) * 2;
#pragma unroll
    for (int mt = 0; mt < 2; mt++) {
#pragma unroll
        for (int nt = 0; nt < 8; nt++) {
            int f = wn0 + nt * 8 + ocol;
            int r1 = r0 + wm0 + mt * 16 + orow;
            int n1 = r1 & (Nn - 1), c1 = r1 >> 12;
            *(float2*)(out + (size_t)n1 * 512 + c1 * OUTF + f) =
                make_float2(acc[mt][nt][0] * dsc, acc[mt][nt][1] * dsc);
            int r2 = r1 + 8;
            int n2 = r2 & (Nn - 1), c2 = r2 >> 12;
            *(float2*)(out + (size_t)n2 * 512 + c2 * OUTF + f) =
                make_float2(acc[mt][nt][2] * dsc, acc[mt][nt][3] * dsc);
        }
    }
#undef LOADG
#undef STORES
#undef CPB
}

// ---------------- launch ----------------
extern "C" void kernel_launch(void* const* d_in, const int* in_sizes, int n_in,
                              void* d_out, int out_size) {
    const float* x = (const float*)d_in[0];
    const float* att = (const float*)d_in[1];
    const float* W = (const float*)d_in[2];
    const unsigned char* mask = (const unsigned char*)d_in[3];
    float* out = (float*)d_out;

    static const int SMEM2 = 65536;
    cudaFuncSetAttribute(k_gemm2m, cudaFuncAttributeMaxDynamicSharedMemorySize, SMEM2);

    k_detect<<<1, 256>>>(mask);
    k_wt<<<256, 256>>>(W);
    k_gemm1<<<128, 256>>>(x);
    k_meanpart<<<1024, 256>>>((const float4*)att);
    k_meanfin<<<1, 256>>>();
    k_colsum<<<dim3(16, 64), 256>>>(att);
    k_rs<<<16, 256>>>();
    k_bprep<<<dim3(128, 4), 256>>>();
    k_gemm2m<<<128, 256, SMEM2>>>(att, mask, out);
}